// round 6
// baseline (speedup 1.0000x reference)
#include <cuda_runtime.h>
#include <math.h>
#include <stdint.h>

#define HIDDEN 3072
#define NH     32
#define HD     96
#define OPSZ   9216   // 32*96 + 2*32*96
#define BB     2
#define LL     2048
#define MTOK   4096   // BB*LL

// ---------------- scratch (static device globals; no allocation) ----------------
__device__ float g_qkv[(size_t)MTOK * OPSZ];     // [token, 9216] : q | k | v
__device__ float g_attn[(size_t)MTOK * HIDDEN];  // [token, 3072] (tf32-rounded)
__device__ float g_x  [(size_t)MTOK * HIDDEN];   // tf32-rounded x
__device__ float g_wq [(size_t)OPSZ * HIDDEN];   // tf32-rounded Wqkv
__device__ float g_wo [(size_t)HIDDEN * HIDDEN]; // tf32-rounded Wo
__device__ float g_cos[LL * 48];
__device__ float g_sin[LL * 48];

__device__ __forceinline__ float tf32r(float x) {
    uint32_t u;
    asm("cvt.rna.tf32.f32 %0, %1;" : "=r"(u) : "f"(x));
    return __uint_as_float(u);
}

// ---------------- elementwise tf32 pre-round ----------------
__global__ void round_tf32_kernel(const float* __restrict__ in,
                                  float* __restrict__ outp, int n4) {
    int i = blockIdx.x * blockDim.x + threadIdx.x;
    if (i >= n4) return;
    float4 v = ((const float4*)in)[i];
    v.x = tf32r(v.x); v.y = tf32r(v.y); v.z = tf32r(v.z); v.w = tf32r(v.w);
    ((float4*)outp)[i] = v;
}

// ---------------- RoPE table (double precision phases) ----------------
__global__ void rope_table_kernel() {
    int idx = blockIdx.x * blockDim.x + threadIdx.x;
    if (idx >= LL * 48) return;
    int i = idx % 48;
    int l = idx / 48;
    double invf = exp(-(double)i / 48.0 * log(10000.0));
    double ang  = (double)l * invf;
    double S    = sqrt(17.0 / 12.0);   // sqrt(1 + ln32/ln4096)
    double s, c;
    sincos(ang, &s, &c);
    g_cos[idx] = (float)(c * S);
    g_sin[idx] = (float)(s * S);
}

// ---------------- RoPE apply (in-place on q,k slices of g_qkv) ----------------
__global__ void rope_apply_kernel() {
    int idx = blockIdx.x * blockDim.x + threadIdx.x;
    const int total = MTOK * NH * 48;
    if (idx >= total) return;
    int i = idx % 48;
    int h = (idx / 48) % NH;
    int t = idx / (48 * NH);
    int l = t & (LL - 1);
    float c = g_cos[l * 48 + i];
    float s = g_sin[l * 48 + i];
    float* qb = g_qkv + (size_t)t * OPSZ + h * HD;
    float q0 = qb[i], q1 = qb[i + 48];
    qb[i]      = q0 * c - q1 * s;
    qb[i + 48] = q1 * c + q0 * s;
    float* kb = qb + 3072;
    float k0 = kb[i], k1 = kb[i + 48];
    kb[i]      = k0 * c - k1 * s;
    kb[i + 48] = k1 * c + k0 * s;
}

// ---------------- TF32 tensor-core GEMM: C[M,N] = A[M,K] * B[N,K]^T ----------------
// BM=128, BN=256, BK=32. 256 threads = 8 warps in 2(M) x 4(N); warp tile 64x64.
// Two-stage cp.async pipeline, ONE __syncthreads per 32-k iteration.
// Smem row-major pitch 36 floats: 16B-aligned rows for cp.async, and fragment
// LDS bank = (4g + tk) mod 32 -> all 32 lanes distinct (conflict-free).
// Inputs must already be tf32-rounded.

#define GPITCH 36
#define ASTAGE (128 * GPITCH)   // 4608 floats
#define BSTAGE (256 * GPITCH)   // 9216 floats
#define GEMM_SMEM_BYTES ((2 * ASTAGE + 2 * BSTAGE) * 4)  // 110,592 B

__device__ __forceinline__ void cp16(uint32_t dst, const float* src) {
    asm volatile("cp.async.cg.shared.global [%0], [%1], 16;\n" :: "r"(dst), "l"(src));
}

__device__ __forceinline__ void mma_tf32(
    float& d0, float& d1, float& d2, float& d3,
    uint32_t a0, uint32_t a1, uint32_t a2, uint32_t a3,
    uint32_t b0, uint32_t b1)
{
    asm volatile(
        "mma.sync.aligned.m16n8k8.row.col.f32.tf32.tf32.f32 "
        "{%0,%1,%2,%3}, {%4,%5,%6,%7}, {%8,%9}, {%0,%1,%2,%3};"
        : "+f"(d0), "+f"(d1), "+f"(d2), "+f"(d3)
        : "r"(a0), "r"(a1), "r"(a2), "r"(a3), "r"(b0), "r"(b1));
}

__global__ __launch_bounds__(256) void gemm_tf32_nt_kernel(
    const float* __restrict__ A, const float* __restrict__ Bm,
    float* __restrict__ C, int M, int N, int K)
{
    extern __shared__ float sm[];
    float* Asm = sm;                   // [2][ASTAGE]
    float* Bsm = sm + 2 * ASTAGE;      // [2][BSTAGE]

    const int tid  = threadIdx.x;
    const int w    = tid >> 5;
    const int lane = tid & 31;
    const int wm   = w >> 2;           // 0..1  (M offset 64)
    const int wn   = w & 3;            // 0..3  (N offset 64)
    const int g    = lane >> 2;        // 0..7
    const int tk   = lane & 3;         // 0..3
    const int bm   = blockIdx.y * 128;
    const int bn   = blockIdx.x * 256;

    // copy assignment: thread t -> row t/2, k-cols (t&1)*16 .. +15 (4 x 16B)
    const int crow = tid >> 1;         // 0..127
    const int ccol = (tid & 1) << 4;   // 0 or 16

    const float* Ap  = A  + (size_t)(bm + crow) * K + ccol;
    const float* Bp  = Bm + (size_t)(bn + crow) * K + ccol;
    const float* Bp2 = Bp + (size_t)128 * K;

    const uint32_t sA  = (uint32_t)__cvta_generic_to_shared(Asm)
                       + (uint32_t)(crow * GPITCH + ccol) * 4u;
    const uint32_t sB  = (uint32_t)__cvta_generic_to_shared(Bsm)
                       + (uint32_t)(crow * GPITCH + ccol) * 4u;
    const uint32_t sB2 = sB + 128u * GPITCH * 4u;

    float acc[4][8][4];
#pragma unroll
    for (int mi = 0; mi < 4; mi++)
#pragma unroll
        for (int ni = 0; ni < 8; ni++)
#pragma unroll
            for (int r = 0; r < 4; r++) acc[mi][ni][r] = 0.0f;

    // prologue: stage 0
#pragma unroll
    for (int c = 0; c < 4; c++) {
        cp16(sA  + c * 16u, Ap  + c * 4);
        cp16(sB  + c * 16u, Bp  + c * 4);
        cp16(sB2 + c * 16u, Bp2 + c * 4);
    }
    asm volatile("cp.async.commit_group;\n" ::: "memory");

    int s = 0;
    for (int kb = 0; kb < K; kb += 32) {
        // stage s's group is the only one pending here
        asm volatile("cp.async.wait_group 0;\n" ::: "memory");
        __syncthreads();   // publish stage s; separates prev-iter reads of s^1 from writes below

        if (kb + 32 < K) {
            const uint32_t so = (uint32_t)(s ^ 1);
            const uint32_t dA  = sA  + so * (ASTAGE * 4u);
            const uint32_t dB  = sB  + so * (BSTAGE * 4u);
            const uint32_t dB2 = sB2 + so * (BSTAGE * 4u);
            const float* a0 = Ap  + kb + 32;
            const float* b0 = Bp  + kb + 32;
            const float* b1 = Bp2 + kb + 32;
#pragma unroll
            for (int c = 0; c < 4; c++) {
                cp16(dA  + c * 16u, a0 + c * 4);
                cp16(dB  + c * 16u, b0 + c * 4);
                cp16(dB2 + c * 16u, b1 + c * 4);
            }
            asm volatile("cp.async.commit_group;\n" ::: "memory");
        }

        const float* Ac = Asm + s * ASTAGE;
        const float* Bc = Bsm + s * BSTAGE;
#pragma unroll
        for (int ks = 0; ks < 4; ks++) {
            const int k0 = ks * 8;
            uint32_t afr[4][4];
            uint32_t bfr[8][2];
#pragma unroll
            for (int mi = 0; mi < 4; mi++) {
                int r = wm * 64 + mi * 16 + g;
                afr[mi][0] = __float_as_uint(Ac[r * GPITCH + k0 + tk]);
                afr[mi][1] = __float_as_uint(Ac[(r + 8) * GPITCH + k0 + tk]);
                afr[mi][2] = __float_as_uint(Ac[r * GPITCH + k0 + tk + 4]);
                afr[mi][3] = __float_as_uint(Ac[(r + 8) * GPITCH + k0 + tk + 4]);
            }
#pragma unroll
            for (int ni = 0; ni < 8; ni++) {
                int c = wn * 64 + ni * 8 + g;
                bfr[ni][0] = __float_as_uint(Bc[c * GPITCH + k0 + tk]);
                bfr[ni][1] = __float_as_uint(Bc[c * GPITCH + k0 + tk + 4]);
            }
#pragma unroll
            for (int mi = 0; mi < 4; mi++)
#pragma unroll
                for (int ni = 0; ni < 8; ni++)
                    mma_tf32(acc[mi][ni][0], acc[mi][ni][1],
                             acc[mi][ni][2], acc[mi][ni][3],
                             afr[mi][0], afr[mi][1], afr[mi][2], afr[mi][3],
                             bfr[ni][0], bfr[ni][1]);
        }
        s ^= 1;
    }

    // epilogue: c0:(g,2tk) c1:(g,2tk+1) c2:(g+8,2tk) c3:(g+8,2tk+1)
#pragma unroll
    for (int mi = 0; mi < 4; mi++) {
#pragma unroll
        for (int ni = 0; ni < 8; ni++) {
            int row = bm + wm * 64 + mi * 16 + g;
            int col = bn + wn * 64 + ni * 8 + tk * 2;
            *(float2*)(C + (size_t)row * N + col) =
                make_float2(acc[mi][ni][0], acc[mi][ni][1]);
            *(float2*)(C + (size_t)(row + 8) * N + col) =
                make_float2(acc[mi][ni][2], acc[mi][ni][3]);
        }
    }
}

// ---------------- fp32 flash attention ----------------
#define BQ 64
#define BKV 64
#define QP 97
#define PP 65
#define FLASH_SMEM_FLOATS (BQ*QP + BKV*QP + BKV*HD + BQ*PP)

__global__ __launch_bounds__(256) void flash_kernel(
    const float* __restrict__ qkv, float* __restrict__ out)
{
    extern __shared__ float sm[];
    float* Qs = sm;
    float* Ks = Qs + BQ * QP;
    float* Vs = Ks + BKV * QP;
    float* Ps = Vs + BKV * HD;

    const int qt  = blockIdx.x;
    const int bh  = blockIdx.y;
    const int b   = bh >> 5;
    const int h   = bh & 31;
    const int tid = threadIdx.x;
    const int ty  = tid >> 4;
    const int tx  = tid & 15;

    const float scale = 0.10206207261596577f;

    const float* qbase = qkv + (size_t)b * LL * OPSZ + h * HD;
    const float* kbase = qbase + 3072;
    const float* vbase = qbase + 6144;

    for (int idx = tid; idx < BQ * HD; idx += 256) {
        int r = idx / HD, d = idx % HD;
        Qs[r * QP + d] = qbase[(size_t)(qt * BQ + r) * OPSZ + d] * scale;
    }

    float m[4], l[4], acc[4][6];
#pragma unroll
    for (int i = 0; i < 4; i++) {
        m[i] = -INFINITY; l[i] = 0.0f;
#pragma unroll
        for (int j = 0; j < 6; j++) acc[i][j] = 0.0f;
    }

    __syncthreads();

    for (int kb = 0; kb <= qt; kb++) {
        __syncthreads();
        for (int idx = tid; idx < BKV * HD; idx += 256) {
            int r = idx / HD, d = idx % HD;
            Ks[r * QP + d] = kbase[(size_t)(kb * BKV + r) * OPSZ + d];
            Vs[r * HD + d] = vbase[(size_t)(kb * BKV + r) * OPSZ + d];
        }
        __syncthreads();

        float s[4][4];
#pragma unroll
        for (int i = 0; i < 4; i++)
#pragma unroll
            for (int j = 0; j < 4; j++) s[i][j] = 0.0f;

#pragma unroll 4
        for (int kk = 0; kk < HD; kk++) {
            float qv[4], kv[4];
#pragma unroll
            for (int i = 0; i < 4; i++) qv[i] = Qs[(ty * 4 + i) * QP + kk];
#pragma unroll
            for (int j = 0; j < 4; j++) kv[j] = Ks[(tx * 4 + j) * QP + kk];
#pragma unroll
            for (int i = 0; i < 4; i++)
#pragma unroll
                for (int j = 0; j < 4; j++)
                    s[i][j] = fmaf(qv[i], kv[j], s[i][j]);
        }

        if (kb == qt) {
#pragma unroll
            for (int i = 0; i < 4; i++) {
                int r = ty * 4 + i;
#pragma unroll
                for (int j = 0; j < 4; j++) {
                    int c = tx * 4 + j;
                    if (c > r) s[i][j] = -INFINITY;
                }
            }
        }

#pragma unroll
        for (int i = 0; i < 4; i++) {
            float mx = fmaxf(fmaxf(s[i][0], s[i][1]), fmaxf(s[i][2], s[i][3]));
#pragma unroll
            for (int off = 8; off >= 1; off >>= 1)
                mx = fmaxf(mx, __shfl_xor_sync(0xffffffffu, mx, off));
            float mnew  = fmaxf(m[i], mx);
            float alpha = __expf(m[i] - mnew);
            float psum = 0.0f;
            int r = ty * 4 + i;
#pragma unroll
            for (int j = 0; j < 4; j++) {
                float p = __expf(s[i][j] - mnew);
                Ps[r * PP + tx * 4 + j] = p;
                psum += p;
            }
#pragma unroll
            for (int off = 8; off >= 1; off >>= 1)
                psum += __shfl_xor_sync(0xffffffffu, psum, off);
            l[i] = l[i] * alpha + psum;
            m[i] = mnew;
#pragma unroll
            for (int j = 0; j < 6; j++) acc[i][j] *= alpha;
        }
        __syncthreads();

#pragma unroll 4
        for (int kk = 0; kk < BKV; kk++) {
            float vv[6];
#pragma unroll
            for (int j = 0; j < 6; j++) vv[j] = Vs[kk * HD + tx * 6 + j];
#pragma unroll
            for (int i = 0; i < 4; i++) {
                float p = Ps[(ty * 4 + i) * PP + kk];
#pragma unroll
                for (int j = 0; j < 6; j++)
                    acc[i][j] = fmaf(p, vv[j], acc[i][j]);
            }
        }
    }

    // write tf32-rounded (feeds the second TF32 GEMM directly)
#pragma unroll
    for (int i = 0; i < 4; i++) {
        int lrow = qt * BQ + ty * 4 + i;
        float inv = 1.0f / l[i];
        float* op = out + (size_t)(b * LL + lrow) * HIDDEN + h * HD + tx * 6;
#pragma unroll
        for (int j = 0; j < 6; j++) op[j] = tf32r(acc[i][j] * inv);
    }
}

// ---------------- launch ----------------
extern "C" void kernel_launch(void* const* d_in, const int* in_sizes, int n_in,
                              void* d_out, int out_size)
{
    const float* x    = (const float*)d_in[0];
    const float* Wqkv = (const float*)d_in[1];
    const float* Wo   = (const float*)d_in[2];
    float* out = (float*)d_out;

    float* qkv;  cudaGetSymbolAddress((void**)&qkv,  g_qkv);
    float* attn; cudaGetSymbolAddress((void**)&attn, g_attn);
    float* xr;   cudaGetSymbolAddress((void**)&xr,   g_x);
    float* wq;   cudaGetSymbolAddress((void**)&wq,   g_wq);
    float* wo;   cudaGetSymbolAddress((void**)&wo,   g_wo);

    static const int flash_smem = FLASH_SMEM_FLOATS * (int)sizeof(float);
    cudaFuncSetAttribute(flash_kernel,
                         cudaFuncAttributeMaxDynamicSharedMemorySize, flash_smem);
    cudaFuncSetAttribute(gemm_tf32_nt_kernel,
                         cudaFuncAttributeMaxDynamicSharedMemorySize, GEMM_SMEM_BYTES);

    // 0) tf32 pre-round of GEMM inputs
    {
        int n4x = MTOK * HIDDEN / 4;
        round_tf32_kernel<<<(n4x + 255) / 256, 256>>>(x, xr, n4x);
        int n4q = OPSZ * HIDDEN / 4;
        round_tf32_kernel<<<(n4q + 255) / 256, 256>>>(Wqkv, wq, n4q);
        int n4o = HIDDEN * HIDDEN / 4;
        round_tf32_kernel<<<(n4o + 255) / 256, 256>>>(Wo, wo, n4o);
    }
    // 1) QKV = x @ Wqkv^T : [4096, 9216]
    {
        dim3 grid(OPSZ / 256, MTOK / 128);
        gemm_tf32_nt_kernel<<<grid, 256, GEMM_SMEM_BYTES>>>(xr, wq, qkv, MTOK, OPSZ, HIDDEN);
    }
    // 2) RoPE
    {
        int n1 = LL * 48;
        rope_table_kernel<<<(n1 + 255) / 256, 256>>>();
        int n2 = MTOK * NH * 48;
        rope_apply_kernel<<<(n2 + 255) / 256, 256>>>();
    }
    // 3) flash attention -> attn [4096, 3072] (tf32-rounded)
    {
        dim3 grid(LL / BQ, BB * NH);
        flash_kernel<<<grid, 256, flash_smem>>>(qkv, attn);
    }
    // 4) out = attn @ Wo^T : [4096, 3072]
    {
        dim3 grid(HIDDEN / 256, MTOK / 128);
        gemm_tf32_nt_kernel<<<grid, 256, GEMM_SMEM_BYTES>>>(attn, wo, out, MTOK, HIDDEN, HIDDEN);
    }
}